// round 7
// baseline (speedup 1.0000x reference)
#include <cuda_runtime.h>
#include <cuda_bf16.h>
#include <math.h>

#define HW   16384
#define NPIX (8 * 16384)

// ---------------- scratch (device globals: no allocation allowed) ----------
__device__ float g_x[8 * 64 * HW];     // fused 1x1 conv output
__device__ float g_off[8 * 18 * HW];   // raw offset conv + bias
__device__ float g_mod[8 * 9 * HW];    // 2*sigmoid(conv + bias)

// ---------------- f32x2 packed helpers ------------------------------------
__device__ __forceinline__ unsigned long long pack2(float lo, float hi) {
    unsigned long long r;
    asm("mov.b64 %0, {%1, %2};" : "=l"(r) : "f"(lo), "f"(hi));
    return r;
}
__device__ __forceinline__ void unpack2(unsigned long long v, float& lo, float& hi) {
    asm("mov.b64 {%0, %1}, %2;" : "=f"(lo), "=f"(hi) : "l"(v));
}
__device__ __forceinline__ unsigned long long fma2(unsigned long long a,
                                                   unsigned long long b,
                                                   unsigned long long c) {
    unsigned long long d;
    asm("fma.rn.f32x2 %0, %1, %2, %3;" : "=l"(d) : "l"(a), "l"(b), "l"(c));
    return d;
}

// ===========================================================================
// Kernel 1: fused 1x1 conv.  4 pixels/thread (px pairs in f32x2 lanes),
// 16 outputs/thread (4 groups).  Weights PRE-DUPLICATED in smem as u64
// (w,w): zero pack ops in the hot loop.  8-channel LDG batches.
// smem: s_w[c*64 + o] = (wf[o,c], wf[o,c])   64KB -> 2 CTAs/SM
// ===========================================================================
__global__ void __launch_bounds__(256, 2)
k1_fuse(const float* __restrict__ x_img,
        const float* __restrict__ x_cont,
        const float* __restrict__ w_fuse) {
    extern __shared__ unsigned long long s_w[];     // 128*64 u64 = 64KB
    for (int idx = threadIdx.x; idx < 128 * 64; idx += blockDim.x) {
        int c = idx >> 6, o = idx & 63;
        float wv = w_fuse[o * 128 + c];
        s_w[idx] = pack2(wv, wv);
    }
    __syncthreads();

    int t = threadIdx.x;
    int g = t >> 6;                                  // output group 0..3
    int q = blockIdx.x * 64 + (t & 63);              // pixel-quad index
    int b  = q >> 12;
    int hw = (q & 4095) << 2;

    const float* xi = x_img  + (size_t)b * 64 * HW + hw;
    const float* xc = x_cont + (size_t)b * 64 * HW + hw;

    unsigned long long acc[32];                      // acc[o*2 + pp]
#pragma unroll
    for (int m = 0; m < 32; m++) acc[m] = 0ULL;

    const unsigned long long* wgrp = s_w + g * 16;

#pragma unroll 1
    for (int c = 0; c < 64; c += 8) {
        float4 xv[8];
#pragma unroll
        for (int u = 0; u < 8; u++)
            xv[u] = *(const float4*)(xi + (size_t)(c + u) * HW);
#pragma unroll
        for (int u = 0; u < 8; u++) {
            unsigned long long s01 = pack2(xv[u].x, xv[u].y);
            unsigned long long s23 = pack2(xv[u].z, xv[u].w);
            const ulonglong2* wrow = (const ulonglong2*)(wgrp + (c + u) * 64);
#pragma unroll
            for (int j = 0; j < 8; j++) {
                ulonglong2 wv = wrow[j];
                acc[(2 * j) * 2 + 0]     = fma2(wv.x, s01, acc[(2 * j) * 2 + 0]);
                acc[(2 * j) * 2 + 1]     = fma2(wv.x, s23, acc[(2 * j) * 2 + 1]);
                acc[(2 * j + 1) * 2 + 0] = fma2(wv.y, s01, acc[(2 * j + 1) * 2 + 0]);
                acc[(2 * j + 1) * 2 + 1] = fma2(wv.y, s23, acc[(2 * j + 1) * 2 + 1]);
            }
        }
    }
#pragma unroll 1
    for (int c = 0; c < 64; c += 8) {
        float4 xv[8];
#pragma unroll
        for (int u = 0; u < 8; u++)
            xv[u] = *(const float4*)(xc + (size_t)(c + u) * HW);
#pragma unroll
        for (int u = 0; u < 8; u++) {
            unsigned long long s01 = pack2(xv[u].x, xv[u].y);
            unsigned long long s23 = pack2(xv[u].z, xv[u].w);
            const ulonglong2* wrow = (const ulonglong2*)(wgrp + (64 + c + u) * 64);
#pragma unroll
            for (int j = 0; j < 8; j++) {
                ulonglong2 wv = wrow[j];
                acc[(2 * j) * 2 + 0]     = fma2(wv.x, s01, acc[(2 * j) * 2 + 0]);
                acc[(2 * j) * 2 + 1]     = fma2(wv.x, s23, acc[(2 * j) * 2 + 1]);
                acc[(2 * j + 1) * 2 + 0] = fma2(wv.y, s01, acc[(2 * j + 1) * 2 + 0]);
                acc[(2 * j + 1) * 2 + 1] = fma2(wv.y, s23, acc[(2 * j + 1) * 2 + 1]);
            }
        }
    }

    float* op = g_x + (size_t)b * 64 * HW + hw;
#pragma unroll
    for (int o = 0; o < 16; o++) {
        float p0, p1, p2, p3;
        unpack2(acc[o * 2 + 0], p0, p1);
        unpack2(acc[o * 2 + 1], p2, p3);
        *(float4*)(op + (size_t)(g * 16 + o) * HW) = make_float4(p0, p1, p2, p3);
    }
}

// ===========================================================================
// Kernel 2: 3x3 conv -> 18 offsets (+bias) and 9 mod (bias + 2*sigmoid).
// (unchanged from R6 — correct, near floor)
// ===========================================================================
__global__ void __launch_bounds__(256, 2)
k2_offmod(const float* __restrict__ w_off,
          const float* __restrict__ w_mod,
          const float* __restrict__ b_off,
          const float* __restrict__ b_mod) {
    extern __shared__ unsigned long long s_w[];     // 64*9*14 u64 = 63KB
    float* s_wf = (float*)s_w;
    for (int idx = threadIdx.x; idx < 64 * 9 * 28; idx += blockDim.x) {
        int c = idx / 252;
        int r = idx % 252;
        int t = r / 28;
        int j = r % 28;
        float v;
        if (j < 18)       v = w_off[((size_t)j * 64 + c) * 9 + t];
        else if (j < 27)  v = w_mod[((size_t)(j - 18) * 64 + c) * 9 + t];
        else              v = 0.0f;
        s_wf[idx] = v;
    }
    __syncthreads();

    int pp = blockIdx.x * blockDim.x + threadIdx.x;  // pixel-pair index
    int b  = pp >> 13;
    int hw = (pp << 1) & 16383;
    int h  = hw >> 7;
    int w0 = hw & 127;                               // even

    int  offs[9];
    bool ok0[9], ok1[9];
#pragma unroll
    for (int t9 = 0; t9 < 9; t9++) {
        int ty = t9 / 3 - 1, tx = t9 % 3 - 1;
        int yy  = h + ty;
        int xx0 = w0 + tx;
        bool rowok = (unsigned)yy < 128u;
        ok0[t9] = rowok && ((unsigned)xx0 < 128u);
        ok1[t9] = rowok && ((unsigned)(xx0 + 1) < 128u);
        offs[t9] = yy * 128 + xx0;
    }

    unsigned long long acc[28];
#pragma unroll
    for (int m = 0; m < 28; m++) acc[m] = 0ULL;

    const float* xb0 = g_x + (size_t)b * 64 * HW;

#pragma unroll 1
    for (int c = 0; c < 64; c++) {
        const float* xb = xb0 + (size_t)c * HW;
#pragma unroll
        for (int t9 = 0; t9 < 9; t9++) {
            float v0 = ok0[t9] ? xb[offs[t9]]     : 0.0f;
            float v1 = ok1[t9] ? xb[offs[t9] + 1] : 0.0f;
            unsigned long long xp0 = pack2(v0, v0);
            unsigned long long xp1 = pack2(v1, v1);
            const unsigned long long* wrow = s_w + (c * 9 + t9) * 14;
#pragma unroll
            for (int jj = 0; jj < 14; jj += 2) {
                ulonglong2 wv = *(const ulonglong2*)(wrow + jj);
                acc[2 * jj + 0]       = fma2(wv.x, xp0, acc[2 * jj + 0]);
                acc[2 * jj + 1]       = fma2(wv.x, xp1, acc[2 * jj + 1]);
                acc[2 * (jj + 1) + 0] = fma2(wv.y, xp0, acc[2 * (jj + 1) + 0]);
                acc[2 * (jj + 1) + 1] = fma2(wv.y, xp1, acc[2 * (jj + 1) + 1]);
            }
        }
    }

    float e0[28], e1[28];
#pragma unroll
    for (int jj = 0; jj < 14; jj++) {
        float a, bb;
        unpack2(acc[2 * jj + 0], a, bb);  e0[2 * jj] = a;  e0[2 * jj + 1] = bb;
        unpack2(acc[2 * jj + 1], a, bb);  e1[2 * jj] = a;  e1[2 * jj + 1] = bb;
    }

#pragma unroll
    for (int j = 0; j < 18; j++) {
        float bo = b_off[j];
        *(unsigned long long*)(g_off + ((size_t)b * 18 + j) * HW + hw)
            = pack2(e0[j] + bo, e1[j] + bo);
    }
#pragma unroll
    for (int j = 0; j < 9; j++) {
        float bm = b_mod[j];
        float m0 = 2.0f / (1.0f + __expf(-(e0[18 + j] + bm)));
        float m1 = 2.0f / (1.0f + __expf(-(e1[18 + j] + bm)));
        *(unsigned long long*)(g_mod + ((size_t)b * 9 + j) * HW + hw)
            = pack2(m0, m1);
    }
}

// ---------------- k3 inner helpers (inlined) ------------------------------
// Gather 2 channels x 2 pixels x 4 corners = 16 scalar LDG into dst[16].
__device__ __forceinline__ void gather2ch(const float* __restrict__ xb, int cbase,
                                          const int* __restrict__ ca0,
                                          const int* __restrict__ ca1,
                                          float* __restrict__ dst) {
#pragma unroll
    for (int u = 0; u < 2; u++) {
        const float* pi = xb + (size_t)(cbase + u) * HW;
#pragma unroll
        for (int qq = 0; qq < 4; qq++) dst[u * 8 + qq]     = pi[ca0[qq]];
#pragma unroll
        for (int qq = 0; qq < 4; qq++) dst[u * 8 + 4 + qq] = pi[ca1[qq]];
    }
}

// Consume 2 channels: bilinear combine + 32 FFMA2 (lanes = output pairs).
__device__ __forceinline__ void consume2ch(const float* __restrict__ v,
                                           const float cw[2][4],
                                           const unsigned long long* __restrict__ wk,
                                           int ch,
                                           unsigned long long* __restrict__ acc) {
#pragma unroll
    for (int u = 0; u < 2; u++) {
        const float* vv = v + u * 8;
        float s0 = vv[0] * cw[0][0];
        s0 = fmaf(vv[1], cw[0][1], s0);
        s0 = fmaf(vv[2], cw[0][2], s0);
        s0 = fmaf(vv[3], cw[0][3], s0);
        float s1 = vv[4] * cw[1][0];
        s1 = fmaf(vv[5], cw[1][1], s1);
        s1 = fmaf(vv[6], cw[1][2], s1);
        s1 = fmaf(vv[7], cw[1][3], s1);
        unsigned long long sp0 = pack2(s0, s0);
        unsigned long long sp1 = pack2(s1, s1);
        const ulonglong2* wrow = (const ulonglong2*)(wk + (ch + u) * 16);
#pragma unroll
        for (int j = 0; j < 8; j++) {
            ulonglong2 wv = wrow[j];
            acc[(2 * j) * 2 + 0]     = fma2(wv.x, sp0, acc[(2 * j) * 2 + 0]);
            acc[(2 * j) * 2 + 1]     = fma2(wv.x, sp1, acc[(2 * j) * 2 + 1]);
            acc[(2 * j + 1) * 2 + 0] = fma2(wv.y, sp0, acc[(2 * j + 1) * 2 + 0]);
            acc[(2 * j + 1) * 2 + 1] = fma2(wv.y, sp1, acc[(2 * j + 1) * 2 + 1]);
        }
    }
}

// ===========================================================================
// Kernel 3: deformable bilinear sample + GEMM.  2 px/thread, 32 outs/thread
// in f32x2 LANES (output pairs from u64 smem weights -> zero weight packs),
// 2 output-group CTAs.  Gathers software-pipelined (1-deep, 16 in flight).
// smem: s_wp[k][i][j] = (w_reg[g*32+2j, i, k], w_reg[g*32+2j+1, i, k]) 73.7KB
// ===========================================================================
__global__ void __launch_bounds__(256, 2)
k3_deform(const float* __restrict__ w_reg,
          float* __restrict__ out) {
    extern __shared__ unsigned long long s_wp[];    // 9*64*16 u64 = 73.7KB
    int g  = blockIdx.x & 1;                         // output group
    int pb = blockIdx.x >> 1;
    for (int idx = threadIdx.x; idx < 9 * 64 * 16; idx += blockDim.x) {
        int j = idx & 15;
        int r = idx >> 4;
        int i = r & 63;
        int k = r >> 6;
        int o0 = g * 32 + 2 * j;
        s_wp[idx] = pack2(w_reg[(size_t)o0 * 576 + i * 9 + k],
                          w_reg[(size_t)(o0 + 1) * 576 + i * 9 + k]);
    }
    __syncthreads();

    int pp = pb * 256 + threadIdx.x;                 // pixel-pair index
    int b  = pp >> 13;
    int hw = (pp & 8191) << 1;
    int h  = hw >> 7;
    int w0 = hw & 127;

    const float* xb   = g_x   + (size_t)b * 64 * HW;
    const float* offp = g_off + (size_t)b * 18 * HW + hw;
    const float* modp = g_mod + (size_t)b * 9 * HW + hw;

    unsigned long long acc[32];                      // acc[j*2 + px], j = out pair
#pragma unroll
    for (int m = 0; m < 32; m++) acc[m] = 0ULL;

    float2 dy2 = *(const float2*)(offp);
    float2 dx2 = *(const float2*)(offp + (size_t)HW);
    float2 mk2 = *(const float2*)(modp);

#pragma unroll 1
    for (int k = 0; k < 9; k++) {
        float2 ndy = make_float2(0.f, 0.f), ndx = ndy, nmk = ndy;
        if (k < 8) {
            ndy = *(const float2*)(offp + (size_t)(2 * k + 2) * HW);
            ndx = *(const float2*)(offp + (size_t)(2 * k + 3) * HW);
            nmk = *(const float2*)(modp + (size_t)(k + 1) * HW);
        }

        int ky = k / 3, kx = k % 3;
        float cw[2][4];
        int   ca[2][4];
        float dyv[2] = {dy2.x, dy2.y};
        float dxv[2] = {dx2.x, dx2.y};
        float mkv[2] = {mk2.x, mk2.y};
#pragma unroll
        for (int px = 0; px < 2; px++) {
            float py  = dyv[px] + (float)(h - 1 + ky);
            float pxx = dxv[px] + (float)(w0 + px - 1 + kx);
            float y0f = floorf(py), x0f = floorf(pxx);
            float wy1 = py - y0f, wy0 = 1.0f - wy1;
            float wx1 = pxx - x0f, wx0 = 1.0f - wx1;
            int y0 = (int)y0f, x0 = (int)x0f;
            int y1 = y0 + 1,   x1 = x0 + 1;
            bool vy0 = (unsigned)y0 < 128u, vy1 = (unsigned)y1 < 128u;
            bool vx0 = (unsigned)x0 < 128u, vx1 = (unsigned)x1 < 128u;
            float mk = mkv[px];
            cw[px][0] = (vy0 && vx0) ? wy0 * wx0 * mk : 0.0f;
            cw[px][1] = (vy0 && vx1) ? wy0 * wx1 * mk : 0.0f;
            cw[px][2] = (vy1 && vx0) ? wy1 * wx0 * mk : 0.0f;
            cw[px][3] = (vy1 && vx1) ? wy1 * wx1 * mk : 0.0f;
            int y0c = min(max(y0, 0), 127), y1c = min(max(y1, 0), 127);
            int x0c = min(max(x0, 0), 127), x1c = min(max(x1, 0), 127);
            ca[px][0] = y0c * 128 + x0c;
            ca[px][1] = y0c * 128 + x1c;
            ca[px][2] = y1c * 128 + x0c;
            ca[px][3] = y1c * 128 + x1c;
        }

        const unsigned long long* wk = s_wp + (size_t)k * 64 * 16;

        // 1-deep software-pipelined gather chunks (2 channels per chunk)
        float v0[16], v1[16];
        gather2ch(xb, 0, ca[0], ca[1], v0);
#pragma unroll 1
        for (int c0 = 0; c0 < 64; c0 += 4) {
            gather2ch(xb, c0 + 2, ca[0], ca[1], v1);
            consume2ch(v0, cw, wk, c0, acc);
            if (c0 + 4 < 64) gather2ch(xb, c0 + 4, ca[0], ca[1], v0);
            consume2ch(v1, cw, wk, c0 + 2, acc);
        }

        dy2 = ndy; dx2 = ndx; mk2 = nmk;
    }

    float* ob = out + (size_t)(b * 64 + g * 32) * HW + hw;
#pragma unroll
    for (int j = 0; j < 16; j++) {
#pragma unroll
        for (int px = 0; px < 2; px++) {
            float lo, hi;
            unpack2(acc[j * 2 + px], lo, hi);
            ob[(size_t)(2 * j) * HW + px]     = lo;
            ob[(size_t)(2 * j + 1) * HW + px] = hi;
        }
    }
}

// ===========================================================================
extern "C" void kernel_launch(void* const* d_in, const int* in_sizes, int n_in,
                              void* d_out, int out_size) {
    const float* x_img  = (const float*)d_in[0];
    const float* x_cont = (const float*)d_in[1];
    const float* w_fuse = (const float*)d_in[2];
    const float* w_off  = (const float*)d_in[3];
    const float* b_off  = (const float*)d_in[4];
    const float* w_mod  = (const float*)d_in[5];
    const float* b_mod  = (const float*)d_in[6];
    const float* w_reg  = (const float*)d_in[7];
    float* out = (float*)d_out;

    cudaFuncSetAttribute(k1_fuse,
                         cudaFuncAttributeMaxDynamicSharedMemorySize, 128 * 64 * 8);
    cudaFuncSetAttribute(k2_offmod,
                         cudaFuncAttributeMaxDynamicSharedMemorySize, 64 * 9 * 14 * 8);
    cudaFuncSetAttribute(k3_deform,
                         cudaFuncAttributeMaxDynamicSharedMemorySize, 9 * 64 * 16 * 8);

    // k1: 512 blocks x 256 thr; thread = (pixel-quad, out-group of 16)
    k1_fuse<<<512, 256, 128 * 64 * 8>>>(x_img, x_cont, w_fuse);
    // k2: 256 blocks x 256 thr; thread = pixel-pair
    k2_offmod<<<(NPIX / 2) / 256, 256, 64 * 9 * 14 * 8>>>(w_off, w_mod, b_off, b_mod);
    // k3: 512 blocks x 256 thr; thread = (pixel-pair, out-group of 32)
    k3_deform<<<512, 256, 9 * 64 * 16 * 8>>>(w_reg, out);
}

// round 8
// speedup vs baseline: 1.3030x; 1.3030x over previous
#include <cuda_runtime.h>
#include <cuda_bf16.h>
#include <math.h>

#define HW   16384
#define NPIX (8 * 16384)

// ---------------- scratch (device globals: no allocation allowed) ----------
__device__ float g_x[8 * 64 * HW];     // fused 1x1 conv output
__device__ float g_off[8 * 18 * HW];   // raw offset conv + bias
__device__ float g_mod[8 * 9 * HW];    // 2*sigmoid(conv + bias)

// ---------------- f32x2 packed helpers ------------------------------------
__device__ __forceinline__ unsigned long long pack2(float lo, float hi) {
    unsigned long long r;
    asm("mov.b64 %0, {%1, %2};" : "=l"(r) : "f"(lo), "f"(hi));
    return r;
}
__device__ __forceinline__ void unpack2(unsigned long long v, float& lo, float& hi) {
    asm("mov.b64 {%0, %1}, %2;" : "=f"(lo), "=f"(hi) : "l"(v));
}
__device__ __forceinline__ unsigned long long fma2(unsigned long long a,
                                                   unsigned long long b,
                                                   unsigned long long c) {
    unsigned long long d;
    asm("fma.rn.f32x2 %0, %1, %2, %3;" : "=l"(d) : "l"(a), "l"(b), "l"(c));
    return d;
}

// ===========================================================================
// Kernel 1: fused 1x1 conv (R6 version — proven 78us).
// 4 pixels/thread (px pairs in f32x2 lanes), 16 outputs/thread (4 groups),
// SCALAR weights (64B/thread/channel), 8-channel LDG batches.
// smem: s_wf[c*64 + o] = w_fuse[o*128 + c]   (scalars, 32KB)
// ===========================================================================
__global__ void __launch_bounds__(256, 2)
k1_fuse(const float* __restrict__ x_img,
        const float* __restrict__ x_cont,
        const float* __restrict__ w_fuse) {
    extern __shared__ float s_wf[];                 // 128*64 fl = 32KB
    for (int idx = threadIdx.x; idx < 128 * 64; idx += blockDim.x) {
        int c = idx >> 6, o = idx & 63;
        s_wf[idx] = w_fuse[o * 128 + c];
    }
    __syncthreads();

    int t = threadIdx.x;
    int g = t >> 6;                                  // output group 0..3
    int q = blockIdx.x * 64 + (t & 63);              // pixel-quad index
    int b  = q >> 12;
    int hw = (q & 4095) << 2;

    const float* xi = x_img  + (size_t)b * 64 * HW + hw;
    const float* xc = x_cont + (size_t)b * 64 * HW + hw;

    unsigned long long acc[32];                      // acc[o*2 + pp]
#pragma unroll
    for (int m = 0; m < 32; m++) acc[m] = 0ULL;

    const float* wgrp = s_wf + g * 16;

#pragma unroll 1
    for (int c = 0; c < 64; c += 8) {
        float4 xv[8];
#pragma unroll
        for (int u = 0; u < 8; u++)
            xv[u] = *(const float4*)(xi + (size_t)(c + u) * HW);
#pragma unroll
        for (int u = 0; u < 8; u++) {
            unsigned long long s01 = pack2(xv[u].x, xv[u].y);
            unsigned long long s23 = pack2(xv[u].z, xv[u].w);
            const float4* wrow = (const float4*)(wgrp + (c + u) * 64);
#pragma unroll
            for (int j = 0; j < 4; j++) {
                float4 w4 = wrow[j];
                float we[4] = {w4.x, w4.y, w4.z, w4.w};
#pragma unroll
                for (int e = 0; e < 4; e++) {
                    unsigned long long wd = pack2(we[e], we[e]);
                    int o = j * 4 + e;
                    acc[o * 2 + 0] = fma2(wd, s01, acc[o * 2 + 0]);
                    acc[o * 2 + 1] = fma2(wd, s23, acc[o * 2 + 1]);
                }
            }
        }
    }
#pragma unroll 1
    for (int c = 0; c < 64; c += 8) {
        float4 xv[8];
#pragma unroll
        for (int u = 0; u < 8; u++)
            xv[u] = *(const float4*)(xc + (size_t)(c + u) * HW);
#pragma unroll
        for (int u = 0; u < 8; u++) {
            unsigned long long s01 = pack2(xv[u].x, xv[u].y);
            unsigned long long s23 = pack2(xv[u].z, xv[u].w);
            const float4* wrow = (const float4*)(wgrp + (64 + c + u) * 64);
#pragma unroll
            for (int j = 0; j < 4; j++) {
                float4 w4 = wrow[j];
                float we[4] = {w4.x, w4.y, w4.z, w4.w};
#pragma unroll
                for (int e = 0; e < 4; e++) {
                    unsigned long long wd = pack2(we[e], we[e]);
                    int o = j * 4 + e;
                    acc[o * 2 + 0] = fma2(wd, s01, acc[o * 2 + 0]);
                    acc[o * 2 + 1] = fma2(wd, s23, acc[o * 2 + 1]);
                }
            }
        }
    }

    float* op = g_x + (size_t)b * 64 * HW + hw;
#pragma unroll
    for (int o = 0; o < 16; o++) {
        float p0, p1, p2, p3;
        unpack2(acc[o * 2 + 0], p0, p1);
        unpack2(acc[o * 2 + 1], p2, p3);
        *(float4*)(op + (size_t)(g * 16 + o) * HW) = make_float4(p0, p1, p2, p3);
    }
}

// ===========================================================================
// Kernel 2: 3x3 conv -> 18 offsets (+bias) and 9 mod (bias + 2*sigmoid).
// (unchanged — correct, near floor)
// ===========================================================================
__global__ void __launch_bounds__(256, 2)
k2_offmod(const float* __restrict__ w_off,
          const float* __restrict__ w_mod,
          const float* __restrict__ b_off,
          const float* __restrict__ b_mod) {
    extern __shared__ unsigned long long s_w[];     // 64*9*14 u64 = 63KB
    float* s_wf = (float*)s_w;
    for (int idx = threadIdx.x; idx < 64 * 9 * 28; idx += blockDim.x) {
        int c = idx / 252;
        int r = idx % 252;
        int t = r / 28;
        int j = r % 28;
        float v;
        if (j < 18)       v = w_off[((size_t)j * 64 + c) * 9 + t];
        else if (j < 27)  v = w_mod[((size_t)(j - 18) * 64 + c) * 9 + t];
        else              v = 0.0f;
        s_wf[idx] = v;
    }
    __syncthreads();

    int pp = blockIdx.x * blockDim.x + threadIdx.x;  // pixel-pair index
    int b  = pp >> 13;
    int hw = (pp << 1) & 16383;
    int h  = hw >> 7;
    int w0 = hw & 127;                               // even

    int  offs[9];
    bool ok0[9], ok1[9];
#pragma unroll
    for (int t9 = 0; t9 < 9; t9++) {
        int ty = t9 / 3 - 1, tx = t9 % 3 - 1;
        int yy  = h + ty;
        int xx0 = w0 + tx;
        bool rowok = (unsigned)yy < 128u;
        ok0[t9] = rowok && ((unsigned)xx0 < 128u);
        ok1[t9] = rowok && ((unsigned)(xx0 + 1) < 128u);
        offs[t9] = yy * 128 + xx0;
    }

    unsigned long long acc[28];
#pragma unroll
    for (int m = 0; m < 28; m++) acc[m] = 0ULL;

    const float* xb0 = g_x + (size_t)b * 64 * HW;

#pragma unroll 1
    for (int c = 0; c < 64; c++) {
        const float* xb = xb0 + (size_t)c * HW;
#pragma unroll
        for (int t9 = 0; t9 < 9; t9++) {
            float v0 = ok0[t9] ? xb[offs[t9]]     : 0.0f;
            float v1 = ok1[t9] ? xb[offs[t9] + 1] : 0.0f;
            unsigned long long xp0 = pack2(v0, v0);
            unsigned long long xp1 = pack2(v1, v1);
            const unsigned long long* wrow = s_w + (c * 9 + t9) * 14;
#pragma unroll
            for (int jj = 0; jj < 14; jj += 2) {
                ulonglong2 wv = *(const ulonglong2*)(wrow + jj);
                acc[2 * jj + 0]       = fma2(wv.x, xp0, acc[2 * jj + 0]);
                acc[2 * jj + 1]       = fma2(wv.x, xp1, acc[2 * jj + 1]);
                acc[2 * (jj + 1) + 0] = fma2(wv.y, xp0, acc[2 * (jj + 1) + 0]);
                acc[2 * (jj + 1) + 1] = fma2(wv.y, xp1, acc[2 * (jj + 1) + 1]);
            }
        }
    }

    float e0[28], e1[28];
#pragma unroll
    for (int jj = 0; jj < 14; jj++) {
        float a, bb;
        unpack2(acc[2 * jj + 0], a, bb);  e0[2 * jj] = a;  e0[2 * jj + 1] = bb;
        unpack2(acc[2 * jj + 1], a, bb);  e1[2 * jj] = a;  e1[2 * jj + 1] = bb;
    }

#pragma unroll
    for (int j = 0; j < 18; j++) {
        float bo = b_off[j];
        *(unsigned long long*)(g_off + ((size_t)b * 18 + j) * HW + hw)
            = pack2(e0[j] + bo, e1[j] + bo);
    }
#pragma unroll
    for (int j = 0; j < 9; j++) {
        float bm = b_mod[j];
        float m0 = 2.0f / (1.0f + __expf(-(e0[18 + j] + bm)));
        float m1 = 2.0f / (1.0f + __expf(-(e1[18 + j] + bm)));
        *(unsigned long long*)(g_mod + ((size_t)b * 9 + j) * HW + hw)
            = pack2(m0, m1);
    }
}

// ===========================================================================
// Kernel 3: deformable bilinear sample + GEMM.  2 px/thread, 32 outs/thread.
// R6 structure (no gather pipeline -> no spills) with R7's cheap consume:
// f32x2 lanes = OUTPUT pairs, weights straight from smem as u64 (zero weight
// packs), 2 sample packs per (px,ch).  Same LDS bytes as R6, ~30% fewer ops.
// smem: s_wp[k][i][j] = (w_reg[g*32+2j,i,k], w_reg[g*32+2j+1,i,k])  73.7KB
// ===========================================================================
__global__ void __launch_bounds__(256, 2)
k3_deform(const float* __restrict__ w_reg,
          float* __restrict__ out) {
    extern __shared__ unsigned long long s_wp[];    // 9*64*16 u64 = 73.7KB
    int g  = blockIdx.x & 1;                         // output group
    int pb = blockIdx.x >> 1;
    for (int idx = threadIdx.x; idx < 9 * 64 * 16; idx += blockDim.x) {
        int j = idx & 15;
        int r = idx >> 4;
        int i = r & 63;
        int k = r >> 6;
        int o0 = g * 32 + 2 * j;
        s_wp[idx] = pack2(w_reg[(size_t)o0 * 576 + i * 9 + k],
                          w_reg[(size_t)(o0 + 1) * 576 + i * 9 + k]);
    }
    __syncthreads();

    int pp = pb * 256 + threadIdx.x;                 // pixel-pair index
    int b  = pp >> 13;
    int hw = (pp & 8191) << 1;
    int h  = hw >> 7;
    int w0 = hw & 127;

    const float* xb   = g_x   + (size_t)b * 64 * HW;
    const float* offp = g_off + (size_t)b * 18 * HW + hw;
    const float* modp = g_mod + (size_t)b * 9 * HW + hw;

    unsigned long long acc[32];                      // acc[j*2 + px], j = out pair
#pragma unroll
    for (int m = 0; m < 32; m++) acc[m] = 0ULL;

    float2 dy2 = *(const float2*)(offp);
    float2 dx2 = *(const float2*)(offp + (size_t)HW);
    float2 mk2 = *(const float2*)(modp);

#pragma unroll 1
    for (int k = 0; k < 9; k++) {
        float2 ndy = make_float2(0.f, 0.f), ndx = ndy, nmk = ndy;
        if (k < 8) {
            ndy = *(const float2*)(offp + (size_t)(2 * k + 2) * HW);
            ndx = *(const float2*)(offp + (size_t)(2 * k + 3) * HW);
            nmk = *(const float2*)(modp + (size_t)(k + 1) * HW);
        }

        int ky = k / 3, kx = k % 3;
        float cw[2][4];
        int   ca[2][4];
        float dyv[2] = {dy2.x, dy2.y};
        float dxv[2] = {dx2.x, dx2.y};
        float mkv[2] = {mk2.x, mk2.y};
#pragma unroll
        for (int px = 0; px < 2; px++) {
            float py  = dyv[px] + (float)(h - 1 + ky);
            float pxx = dxv[px] + (float)(w0 + px - 1 + kx);
            float y0f = floorf(py), x0f = floorf(pxx);
            float wy1 = py - y0f, wy0 = 1.0f - wy1;
            float wx1 = pxx - x0f, wx0 = 1.0f - wx1;
            int y0 = (int)y0f, x0 = (int)x0f;
            int y1 = y0 + 1,   x1 = x0 + 1;
            bool vy0 = (unsigned)y0 < 128u, vy1 = (unsigned)y1 < 128u;
            bool vx0 = (unsigned)x0 < 128u, vx1 = (unsigned)x1 < 128u;
            float mk = mkv[px];
            cw[px][0] = (vy0 && vx0) ? wy0 * wx0 * mk : 0.0f;
            cw[px][1] = (vy0 && vx1) ? wy0 * wx1 * mk : 0.0f;
            cw[px][2] = (vy1 && vx0) ? wy1 * wx0 * mk : 0.0f;
            cw[px][3] = (vy1 && vx1) ? wy1 * wx1 * mk : 0.0f;
            int y0c = min(max(y0, 0), 127), y1c = min(max(y1, 0), 127);
            int x0c = min(max(x0, 0), 127), x1c = min(max(x1, 0), 127);
            ca[px][0] = y0c * 128 + x0c;
            ca[px][1] = y0c * 128 + x1c;
            ca[px][2] = y1c * 128 + x0c;
            ca[px][3] = y1c * 128 + x1c;
        }

        const unsigned long long* wk = s_wp + (size_t)k * 64 * 16;

#pragma unroll 1
        for (int i0 = 0; i0 < 64; i0 += 2) {
            // 16 gathers in flight (2 channels x 2 pixels x 4 corners)
            float v[2][8];
#pragma unroll
            for (int u = 0; u < 2; u++) {
                const float* pi = xb + (size_t)(i0 + u) * HW;
#pragma unroll
                for (int px = 0; px < 2; px++) {
                    v[u][px * 4 + 0] = pi[ca[px][0]];
                    v[u][px * 4 + 1] = pi[ca[px][1]];
                    v[u][px * 4 + 2] = pi[ca[px][2]];
                    v[u][px * 4 + 3] = pi[ca[px][3]];
                }
            }
#pragma unroll
            for (int u = 0; u < 2; u++) {
                float s0 = v[u][0] * cw[0][0];
                s0 = fmaf(v[u][1], cw[0][1], s0);
                s0 = fmaf(v[u][2], cw[0][2], s0);
                s0 = fmaf(v[u][3], cw[0][3], s0);
                float s1 = v[u][4] * cw[1][0];
                s1 = fmaf(v[u][5], cw[1][1], s1);
                s1 = fmaf(v[u][6], cw[1][2], s1);
                s1 = fmaf(v[u][7], cw[1][3], s1);
                unsigned long long sp0 = pack2(s0, s0);
                unsigned long long sp1 = pack2(s1, s1);
                const ulonglong2* wrow = (const ulonglong2*)(wk + (i0 + u) * 16);
#pragma unroll
                for (int j = 0; j < 8; j++) {
                    ulonglong2 wv = wrow[j];
                    acc[(2 * j) * 2 + 0]     = fma2(wv.x, sp0, acc[(2 * j) * 2 + 0]);
                    acc[(2 * j) * 2 + 1]     = fma2(wv.x, sp1, acc[(2 * j) * 2 + 1]);
                    acc[(2 * j + 1) * 2 + 0] = fma2(wv.y, sp0, acc[(2 * j + 1) * 2 + 0]);
                    acc[(2 * j + 1) * 2 + 1] = fma2(wv.y, sp1, acc[(2 * j + 1) * 2 + 1]);
                }
            }
        }

        dy2 = ndy; dx2 = ndx; mk2 = nmk;
    }

    float* ob = out + (size_t)(b * 64 + g * 32) * HW + hw;
#pragma unroll
    for (int j = 0; j < 16; j++) {
#pragma unroll
        for (int px = 0; px < 2; px++) {
            float lo, hi;
            unpack2(acc[j * 2 + px], lo, hi);
            ob[(size_t)(2 * j) * HW + px]     = lo;
            ob[(size_t)(2 * j + 1) * HW + px] = hi;
        }
    }
}

// ===========================================================================
extern "C" void kernel_launch(void* const* d_in, const int* in_sizes, int n_in,
                              void* d_out, int out_size) {
    const float* x_img  = (const float*)d_in[0];
    const float* x_cont = (const float*)d_in[1];
    const float* w_fuse = (const float*)d_in[2];
    const float* w_off  = (const float*)d_in[3];
    const float* b_off  = (const float*)d_in[4];
    const float* w_mod  = (const float*)d_in[5];
    const float* b_mod  = (const float*)d_in[6];
    const float* w_reg  = (const float*)d_in[7];
    float* out = (float*)d_out;

    cudaFuncSetAttribute(k2_offmod,
                         cudaFuncAttributeMaxDynamicSharedMemorySize, 64 * 9 * 14 * 8);
    cudaFuncSetAttribute(k3_deform,
                         cudaFuncAttributeMaxDynamicSharedMemorySize, 9 * 64 * 16 * 8);

    // k1: 512 blocks x 256 thr; thread = (pixel-quad, out-group of 16)
    k1_fuse<<<512, 256, 128 * 64 * 4>>>(x_img, x_cont, w_fuse);
    // k2: 256 blocks x 256 thr; thread = pixel-pair
    k2_offmod<<<(NPIX / 2) / 256, 256, 64 * 9 * 14 * 8>>>(w_off, w_mod, b_off, b_mod);
    // k3: 512 blocks x 256 thr; thread = (pixel-pair, out-group of 32)
    k3_deform<<<512, 256, 9 * 64 * 16 * 8>>>(w_reg, out);
}